// round 13
// baseline (speedup 1.0000x reference)
#include <cuda_runtime.h>
#include <cuda_fp16.h>
#include <cstdint>

#define CB   4
#define CTQ  2048
#define CTK  2048
#define CDV  256
#define CQKD 128
#define CH   8
#define COUT 1024

// 0.25 * log2(e): folded into Q projection so softmax exp becomes exp2.
#define SCALE_Q 0.36067376022224085f

// Scratch (device globals: allocation-free). fp16 payloads.
__device__ __half g_Qc[CB*CTQ*1024];              // 16 MB
__device__ __half g_Kc[CB*CTK*1024];              // 16 MB
__device__ __half g_Vct[(size_t)CB*CDV*CTK];      //  4 MB  V^T compacted [b][dv][key]
__device__ __half g_Qlow[CB*CTQ*CQKD];            //  2 MB (pre-scaled by SCALE_Q)
__device__ __half g_Klowc[CB*CTK*CQKD];           //  2 MB compacted (scatter from proj)
__device__ __half g_Obuf[(size_t)CB*CTQ*CH*CDV];  // 32 MB
__device__ __half g_Wqh[CQKD*1024];
__device__ __half g_Wkh[CQKD*1024];
__device__ __half g_Woh[COUT*CH*CDV];
__device__ int    g_cidx[CB*CTK];
__device__ int    g_pos[CB*CTK];
__device__ int    g_nk[CB];

__device__ __forceinline__ void mma16(float* c, const uint32_t* a, const uint32_t* b){
    asm volatile(
      "mma.sync.aligned.m16n8k16.row.col.f32.f16.f16.f32 "
      "{%0,%1,%2,%3},{%4,%5,%6,%7},{%8,%9},{%0,%1,%2,%3};"
      : "+f"(c[0]), "+f"(c[1]), "+f"(c[2]), "+f"(c[3])
      : "r"(a[0]), "r"(a[1]), "r"(a[2]), "r"(a[3]), "r"(b[0]), "r"(b[1]));
}
__device__ __forceinline__ void ldsm4(uint32_t* r, uint32_t saddr){
    asm volatile("ldmatrix.sync.aligned.m8n8.x4.shared.b16 {%0,%1,%2,%3}, [%4];"
      : "=r"(r[0]), "=r"(r[1]), "=r"(r[2]), "=r"(r[3]) : "r"(saddr));
}
__device__ __forceinline__ uint32_t s2u(const void* p){
    return (uint32_t)__cvta_generic_to_shared(p);
}
__device__ __forceinline__ uint32_t pack2(float x, float y){
    __half2 h = __floats2half2_rn(x, y);
    return *(uint32_t*)&h;
}
// half2{2^x, 2^y} from two fp32 exponents
__device__ __forceinline__ uint32_t ex2h2(float x, float y){
    uint32_t h, r;
    asm("cvt.rn.f16x2.f32 %0, %2, %1;" : "=r"(h) : "f"(x), "f"(y));
    asm("ex2.approx.f16x2 %0, %1;" : "=r"(r) : "r"(h));
    return r;
}
__device__ __forceinline__ void cp16(void* s, const void* g){
    unsigned sa = (unsigned)__cvta_generic_to_shared(s);
    asm volatile("cp.async.cg.shared.global [%0], [%1], 16;" :: "r"(sa), "l"(g));
}
#define CP_COMMIT asm volatile("cp.async.commit_group;")
#define CP_WAIT0  asm volatile("cp.async.wait_group 0;")

// One-shot fp32 -> fp16 conversion of all five tensors (grid-stride).
__global__ void cvt_all_kernel(
    const float4* __restrict__ Q,  const float4* __restrict__ K,
    const float4* __restrict__ Wq, const float4* __restrict__ Wk,
    const float4* __restrict__ Wo,
    uint2* __restrict__ oQ, uint2* __restrict__ oK,
    uint2* __restrict__ oWq, uint2* __restrict__ oWk, uint2* __restrict__ oWo)
{
    const int nQ  = CB*CTQ*1024/4;
    const int nW  = CQKD*1024/4;
    const int nWo = COUT*CH*CDV/4;
    const int total = nQ + nQ + nW + nW + nWo;
    for (int i = blockIdx.x*blockDim.x + threadIdx.x; i < total;
         i += gridDim.x*blockDim.x){
        const float4* s; uint2* d; int j = i;
        if (j < nQ){ s = Q; d = oQ; }
        else if ((j -= nQ) < nQ){ s = K; d = oK; }
        else if ((j -= nQ) < nW){ s = Wq; d = oWq; }
        else if ((j -= nW) < nW){ s = Wk; d = oWk; }
        else { j -= nW; s = Wo; d = oWo; }
        float4 v = s[j];
        uint2 o; o.x = pack2(v.x, v.y); o.y = pack2(v.z, v.w);
        d[j] = o;
    }
}

// Per-batch compaction: cidx (dest->src), pos (src->dest or -1), nk;
// also pre-zeroes the Klowc pad rows (rows nk..align32-1).
__global__ void compact_kernel(const int* __restrict__ mask,
                               int* __restrict__ cidx, int* __restrict__ pos,
                               int* __restrict__ nk, __half* __restrict__ Klowc){
    __shared__ int wsum[32];
    int b = blockIdx.x, t = threadIdx.x;          // 1024 threads, 2 keys each
    int f0 = (mask[b*CTK + 2*t]     == 0);
    int f1 = (mask[b*CTK + 2*t + 1] == 0);
    int c = f0 + f1;
    int lane = t & 31, wid = t >> 5;
    int x = c;
    #pragma unroll
    for (int o = 1; o < 32; o <<= 1){
        int y = __shfl_up_sync(0xffffffffu, x, o);
        if (lane >= o) x += y;
    }
    if (lane == 31) wsum[wid] = x;
    __syncthreads();
    if (wid == 0){
        int y = wsum[lane];
        #pragma unroll
        for (int o = 1; o < 32; o <<= 1){
            int z = __shfl_up_sync(0xffffffffu, y, o);
            if (lane >= o) y += z;
        }
        wsum[lane] = y;
    }
    __syncthreads();
    int excl = x - c + (wid ? wsum[wid-1] : 0);
    pos[b*CTK + 2*t]     = f0 ? excl : -1;
    pos[b*CTK + 2*t + 1] = f1 ? (excl + f0) : -1;
    if (f0) cidx[b*CTK + excl]      = 2*t;
    if (f1) cidx[b*CTK + excl + f0] = 2*t + 1;
    int nkb = wsum[31];
    if (t == 0) nk[b] = nkb;
    int npadrows = ((nkb + 31) & ~31) - nkb;
    for (int idx = t; idx < npadrows*16; idx += 1024){
        int row = nkb + (idx >> 4), col = (idx & 15) * 8;
        *(uint4*)&Klowc[((size_t)b*CTK + row)*CQKD + col] = make_uint4(0,0,0,0);
    }
}

// Fused gather + transpose + fp16 cvt: Vct[b][dv][j] = fp16(V[b][cidx[j]][dv]), 0 pads.
__global__ void gathervt_kernel(const float* __restrict__ V,
                                const int* __restrict__ cidx, const int* __restrict__ nk,
                                __half* __restrict__ Vct){
    __shared__ __half tile[32][33];
    int b = blockIdx.z, kt = blockIdx.x, dt = blockIdx.y;
    int tx = threadIdx.x, ty = threadIdx.y;       // 32 x 8
    int nkb = nk[b];
    int j0 = kt*32;
    if (j0 >= ((nkb + 31) & ~31)) return;
    #pragma unroll
    for (int jj = ty; jj < 32; jj += 8){
        int j = j0 + jj;
        __half hv = __float2half_rn(0.f);
        if (j < nkb)
            hv = __float2half_rn(V[((size_t)b*CTK + cidx[b*CTK + j])*CDV + dt*32 + tx]);
        tile[jj][tx] = hv;
    }
    __syncthreads();
    #pragma unroll
    for (int dd = ty; dd < 32; dd += 8)
        Vct[((size_t)b*CDV + dt*32 + dd)*CTK + j0 + tx] = tile[tx][dd];
}

// C[M][N] = scl*(A[M][K] @ B[N][K]^T + bias[N]).  fp16 m16n8k16 + ldmatrix.
// 256 threads / 8 warps: 4 m-strips x 2 n-halves; warp tile 32 x BN/2.
// BM=128, BK=32. SCATTER && z==1: row r stored at compacted row pos[r].
template<int BN, bool HALF_OUT, bool SCATTER>
__global__ void __launch_bounds__(256,2) gemm_kernel(
    const __half* __restrict__ A0, const __half* __restrict__ A1,
    const __half* __restrict__ B0, const __half* __restrict__ B1,
    const float* __restrict__ bias0, const float* __restrict__ bias1,
    void* __restrict__ C0, void* __restrict__ C1, int K,
    float scl0, float scl1, const int* __restrict__ pos)
{
    const __half* A    = blockIdx.z ? A1 : A0;
    const __half* B    = blockIdx.z ? B1 : B0;
    const float*  bias = blockIdx.z ? bias1 : bias0;
    void*         C    = blockIdx.z ? C1 : C0;
    const float   scl  = blockIdx.z ? scl1 : scl0;
    const int N = gridDim.x * BN;

    extern __shared__ char sm[];
    uint32_t* As = (uint32_t*)sm;                 // [2][128][20] words (80B rows)
    uint32_t* Bs = As + 2*128*20;                 // [2][BN][20]

    const int m0 = blockIdx.y*128, n0 = blockIdx.x*BN;
    const int t = threadIdx.x, lane = t & 31, w = t >> 5;
    const int cq = lane & 3;
    const int wm = w & 3, wn = w >> 2;
    constexpr int NF = BN/16;                     // per-warp n fragments

    const uint32_t asb = s2u(As);
    const uint32_t bsb = asb + 2*128*80;
    const int j8 = lane & 7, mq = lane >> 3;
    const uint32_t aoffL = (uint32_t)(wm*32 + j8 + ((mq&1)<<3))*80 + ((mq>>1)<<4);
    const uint32_t boffL = (uint32_t)(wn*(BN/2) + j8 + ((mq>>1)<<3))*80 + ((mq&1)<<4);

    float acc[2][NF][4];
    #pragma unroll
    for (int i=0;i<2;i++)
      #pragma unroll
      for (int j=0;j<NF;j++)
        #pragma unroll
        for (int r=0;r<4;r++) acc[i][j][r]=0.f;

    auto load = [&](int s, int k0){
        #pragma unroll
        for (int i=0;i<2;i++){                    // A tile 128x32 halves (512 cp16)
            int id = t + i*256;
            int r = id>>2, c = (id&3)*8;
            cp16(&As[s*2560 + r*20 + c/2], A + (size_t)(m0+r)*K + k0 + c);
        }
        #pragma unroll
        for (int i=0;i<BN/64;i++){                // B tile BNx32 halves (BN*4 cp16)
            int id = t + i*256;
            int r = id>>2, c = (id&3)*8;
            cp16(&Bs[s*BN*20 + r*20 + c/2], B + (size_t)(n0+r)*K + k0 + c);
        }
    };

    load(0, 0); CP_COMMIT;
    const int NKt = K/32;
    for (int kt = 0; kt < NKt; kt++){
        int s = kt & 1;
        CP_WAIT0;
        __syncthreads();
        if (kt + 1 < NKt){ load(s^1, (kt+1)*32); CP_COMMIT; }
        const uint32_t asS = asb + s*10240;
        const uint32_t bsS = bsb + s*BN*80;
        #pragma unroll
        for (int ks = 0; ks < 2; ks++){
            uint32_t a[2][4];
            ldsm4(a[0], asS + aoffL + ks*32);
            ldsm4(a[1], asS + aoffL + 16*80 + ks*32);
            #pragma unroll
            for (int nfp = 0; nfp < NF/2; nfp++){
                uint32_t bb[4];
                ldsm4(bb, bsS + boffL + nfp*16*80 + ks*32);
                mma16(acc[0][2*nfp],   a[0], bb);
                mma16(acc[1][2*nfp],   a[1], bb);
                mma16(acc[0][2*nfp+1], a[0], bb+2);
                mma16(acc[1][2*nfp+1], a[1], bb+2);
            }
        }
        __syncthreads();
    }

    #pragma unroll
    for (int mf = 0; mf < 2; mf++){
        int r = m0 + wm*32 + mf*16 + (lane>>2);
        size_t ro0 = (size_t)r*N, ro1 = (size_t)(r+8)*N;
        bool st0 = true, st1 = true;
        if (SCATTER && blockIdx.z == 1){
            int bidx = r >> 11;                   // CTK = 2048
            int d0 = pos[r], d1 = pos[r+8];
            st0 = d0 >= 0; st1 = d1 >= 0;
            ro0 = (size_t)(bidx*CTK + (st0 ? d0 : 0))*N;
            ro1 = (size_t)(bidx*CTK + (st1 ? d1 : 0))*N;
        }
        #pragma unroll
        for (int nf = 0; nf < NF; nf++){
            int c = n0 + wn*(BN/2) + nf*8 + (cq<<1);
            float b0 = bias[c], b1 = bias[c+1];
            float v0 = (acc[mf][nf][0]+b0)*scl, v1 = (acc[mf][nf][1]+b1)*scl;
            float v2 = (acc[mf][nf][2]+b0)*scl, v3 = (acc[mf][nf][3]+b1)*scl;
            if (HALF_OUT){
                __half* Ch = (__half*)C;
                if (st0) *(uint32_t*)(Ch + ro0 + c) = pack2(v0, v1);
                if (st1) *(uint32_t*)(Ch + ro1 + c) = pack2(v2, v3);
            } else {
                float* Cf = (float*)C;
                *(float2*)(Cf + ro0 + c) = make_float2(v0, v1);
                *(float2*)(Cf + ro1 + c) = make_float2(v2, v3);
            }
        }
    }
}

// ---------- Flash attention over compacted keys (fp16 mma + ldmatrix) ----------
// dv-split: blockIdx.z picks V half (128 dv rows). 128 thr / 4 warps,
// 64 q rows/block, 32 keys/tile. 3 blocks/SM.  (identical to R12)
#define OFF_VS  0                  // [2][128][40]h = 20480 B
#define OFF_KS  20480              // [2][32][24]h  =  3072 B
#define OFF_PS  23552              // [64][40]h     =  5120 B (Q staged here pre-loop)
#define OFF_LI  28672              // [64]f         =   256 B
#define FLASH_SMEM 28928

__device__ __forceinline__ void flash_load(char* sm, int s, int key0,
    const __half* Vtb, const __half* Kl, int t)
{
    char* VsB = sm + OFF_VS + s*10240;
    #pragma unroll
    for (int i = 0; i < 4; i++){                  // 128 dv rows x 32 keys (64B)
        int id = t + i*128;
        int dv = id>>2, c = (id&3)*8;             // halves
        cp16(VsB + dv*80 + c*2, Vtb + (size_t)dv*CTK + key0 + c);
    }
    if (t < 64){                                  // K tile 32x16 halves
        int r = t>>1, c = (t&1)*8;
        cp16(sm + OFF_KS + s*1536 + r*48 + c*2, Kl + (size_t)(key0 + r)*CQKD + c);
    }
}

__global__ void __launch_bounds__(128,3) flash_kernel(const int* __restrict__ nkarr)
{
    extern __shared__ char sm[];
    uint32_t* Ks  = (uint32_t*)(sm + OFF_KS);     // row stride 12 words
    uint32_t* Ps  = (uint32_t*)(sm + OFF_PS);     // row stride 20 words
    float*    lInv= (float*)   (sm + OFF_LI);

    const int t = threadIdx.x, lane = t & 31, w = t >> 5;
    const int cq = lane & 3;
    const int q0 = blockIdx.x * 64;
    const int b  = blockIdx.y >> 3, h = blockIdx.y & 7;
    const int z  = blockIdx.z;                    // dv half

    const int nkb = __ldg(&nkarr[b]);
    const int NT  = (nkb + 31) >> 5;
    const float npad = (float)(NT*32 - nkb);

    const __half* Vtb = g_Vct   + (size_t)b*CDV*CTK + (size_t)(z*128)*CTK;
    const __half* Kl  = g_Klowc + (size_t)b*CTK*CQKD + h*16;

    flash_load(sm, 0, 0, Vtb, Kl, t);
    CP_COMMIT;

    // Stage Q tile (64x16 halves) into Ps region (stride 12 words).
    {
        int r = t>>1;
        const uint4* src = (const uint4*)(g_Qlow + (size_t)(b*CTQ + q0 + r)*CQKD + h*16);
        *(uint4*)&Ps[r*12 + (t&1)*4] = src[t&1];
    }
    __syncthreads();
    uint32_t qa[4];
    {
        int r = w*16 + (lane>>2);
        qa[0] = Ps[r*12 + cq];       qa[1] = Ps[(r+8)*12 + cq];
        qa[2] = Ps[r*12 + cq + 4];   qa[3] = Ps[(r+8)*12 + cq + 4];
    }

    const int wm = w >> 1, wn = w & 1;            // P@V map: rows wm*32, cols wn*64
    const uint32_t vsb = s2u(sm + OFF_VS);
    const uint32_t psb = s2u(sm + OFF_PS);
    const int j8 = lane & 7, mq = lane >> 3;
    const uint32_t aoffL = (uint32_t)(wm*32 + j8 + ((mq&1)<<3))*80 + ((mq>>1)<<4);
    const uint32_t boffL = (uint32_t)(wn*64 + j8 + ((mq>>1)<<3))*80 + ((mq&1)<<4);

    float acc[2][8][4];
    #pragma unroll
    for (int i=0;i<2;i++)
      #pragma unroll
      for (int j=0;j<8;j++)
        #pragma unroll
        for (int r=0;r<4;r++) acc[i][j][r]=0.f;
    float accL[2][4];                             // ones-MMA row-sum accumulators
    #pragma unroll
    for (int i=0;i<2;i++)
      #pragma unroll
      for (int r=0;r<4;r++) accL[i][r]=0.f;
    const uint32_t ones2[2] = {0x3C003C00u, 0x3C003C00u};

    for (int kt = 0; kt < NT; kt++){
        int s = kt & 1;
        CP_WAIT0;
        __syncthreads();
        if (kt + 1 < NT){ flash_load(sm, s^1, (kt+1)*32, Vtb, Kl, t); CP_COMMIT; }

        // --- scores (exp2 units): rows w*16..+15, 32 cols; 4 mma ---
        {
            const uint32_t* KsS = Ks + s*384;
            int r = w*16 + (lane>>2);
            #pragma unroll
            for (int j = 0; j < 4; j++){
                float c0[4] = {0.f,0.f,0.f,0.f};
                int n = j*8 + (lane>>2);
                uint32_t bb[2];
                bb[0] = KsS[n*12 + cq];
                bb[1] = KsS[n*12 + cq + 4];
                mma16(c0, qa, bb);
                Ps[r*20 + j*4 + cq]     = ex2h2(c0[0], c0[1]);
                Ps[(r+8)*20 + j*4 + cq] = ex2h2(c0[2], c0[3]);
            }
        }
        __syncthreads();

        // --- P(64x32) @ V(32x128 half) + ones-MMA row sums ---
        {
            const uint32_t vsS = vsb + s*10240;
            #pragma unroll
            for (int ks = 0; ks < 2; ks++){
                uint32_t a[2][4];
                ldsm4(a[0], psb + aoffL + ks*32);
                ldsm4(a[1], psb + aoffL + 16*80 + ks*32);
                mma16(accL[0], a[0], ones2);
                mma16(accL[1], a[1], ones2);
                #pragma unroll
                for (int nfp = 0; nfp < 4; nfp++){
                    uint32_t bb[4];
                    ldsm4(bb, vsS + boffL + nfp*16*80 + ks*32);
                    mma16(acc[0][2*nfp],   a[0], bb);
                    mma16(acc[1][2*nfp],   a[1], bb);
                    mma16(acc[0][2*nfp+1], a[0], bb+2);
                    mma16(acc[1][2*nfp+1], a[1], bb+2);
                }
            }
        }
    }

    // Row-sum inverses from accL (wn=0 writes; identical in both z blocks).
    if (wn == 0 && cq == 0){
        #pragma unroll
        for (int mf = 0; mf < 2; mf++){
            int r = wm*32 + mf*16 + (lane>>2);
            lInv[r]     = 1.f / (accL[mf][0] - npad);
            lInv[r + 8] = 1.f / (accL[mf][2] - npad);
        }
    }
    __syncthreads();

    #pragma unroll
    for (int mf = 0; mf < 2; mf++){
        int rl = wm*32 + mf*16 + (lane>>2);
        float i0 = lInv[rl], i1 = lInv[rl+8];
        __half* row0 = g_Obuf + (size_t)(b*CTQ + q0 + rl)    *(CH*CDV) + h*CDV;
        __half* row1 = g_Obuf + (size_t)(b*CTQ + q0 + rl + 8)*(CH*CDV) + h*CDV;
        #pragma unroll
        for (int nf = 0; nf < 8; nf++){
            int c2 = z*128 + wn*64 + nf*8 + (cq<<1);
            *(uint32_t*)(row0 + c2) = pack2(acc[mf][nf][0]*i0, acc[mf][nf][1]*i0);
            *(uint32_t*)(row1 + c2) = pack2(acc[mf][nf][2]*i1, acc[mf][nf][3]*i1);
        }
    }
}

static const int GEMM_SMEM_64  = (2*128*20 + 2*64*20)*4;    // 30720
static const int GEMM_SMEM_128 = (2*128*20 + 2*128*20)*4;   // 40960

extern "C" void kernel_launch(void* const* d_in, const int* in_sizes, int n_in,
                              void* d_out, int out_size)
{
    const float* Q    = (const float*)d_in[0];
    const float* K    = (const float*)d_in[1];
    const float* V    = (const float*)d_in[2];
    const int*   mask = (const int*)  d_in[3];
    const float* Wq   = (const float*)d_in[4];
    const float* bq   = (const float*)d_in[5];
    const float* Wk   = (const float*)d_in[6];
    const float* bk   = (const float*)d_in[7];
    const float* Wo   = (const float*)d_in[8];
    const float* bo   = (const float*)d_in[9];
    float* out = (float*)d_out;

    __half *dQc,*dKc,*dVct,*dQlow,*dKlowc,*dObuf,*dWqh,*dWkh,*dWoh;
    int *dCidx,*dPos,*dNk;
    cudaGetSymbolAddress((void**)&dQc,    g_Qc);
    cudaGetSymbolAddress((void**)&dKc,    g_Kc);
    cudaGetSymbolAddress((void**)&dVct,   g_Vct);
    cudaGetSymbolAddress((void**)&dQlow,  g_Qlow);
    cudaGetSymbolAddress((void**)&dKlowc, g_Klowc);
    cudaGetSymbolAddress((void**)&dObuf,  g_Obuf);
    cudaGetSymbolAddress((void**)&dWqh,   g_Wqh);
    cudaGetSymbolAddress((void**)&dWkh,   g_Wkh);
    cudaGetSymbolAddress((void**)&dWoh,   g_Woh);
    cudaGetSymbolAddress((void**)&dCidx,  g_cidx);
    cudaGetSymbolAddress((void**)&dPos,   g_pos);
    cudaGetSymbolAddress((void**)&dNk,    g_nk);

    cudaFuncSetAttribute((const void*)gemm_kernel<64,true,true>,
                         cudaFuncAttributeMaxDynamicSharedMemorySize, GEMM_SMEM_64);
    cudaFuncSetAttribute((const void*)gemm_kernel<128,false,false>,
                         cudaFuncAttributeMaxDynamicSharedMemorySize, GEMM_SMEM_128);
    cudaFuncSetAttribute((const void*)flash_kernel,
                         cudaFuncAttributeMaxDynamicSharedMemorySize, FLASH_SMEM);

    // One merged fp16 conversion for Q, K, Wq, Wk, Wo
    cvt_all_kernel<<<2048,256>>>(
        (const float4*)Q, (const float4*)K,
        (const float4*)Wq, (const float4*)Wk, (const float4*)Wo,
        (uint2*)dQc, (uint2*)dKc, (uint2*)dWqh, (uint2*)dWkh, (uint2*)dWoh);

    // Mask compaction + V gather/transpose
    compact_kernel<<<CB, 1024>>>(mask, dCidx, dPos, dNk, dKlowc);
    gathervt_kernel<<<dim3(CTK/32, CDV/32, CB), dim3(32,8)>>>(V, dCidx, dNk, dVct);

    // Fused Q/K projections (8 warps): Q pre-scaled; K scatter-stored compacted
    gemm_kernel<64,true,true><<<dim3(2, 64, 2), 256, GEMM_SMEM_64>>>(
        dQc, dKc, dWqh, dWkh, bq, bk, dQlow, dKlowc, 1024, SCALE_Q, 1.0f, dPos);

    // Flash: dv-split (z in {0,1}), 3 blocks/SM
    flash_kernel<<<dim3(CTQ/64, CB*CH, 2), 128, FLASH_SMEM>>>(dNk);

    // Final GEMM (8 warps)
    gemm_kernel<128,false,false><<<dim3(8, 64, 1), 256, GEMM_SMEM_128>>>(
        dObuf, dObuf, dWoh, dWoh, bo, bo, out, out, 2048, 1.0f, 1.0f, nullptr);
}

// round 14
// speedup vs baseline: 1.5591x; 1.5591x over previous
#include <cuda_runtime.h>
#include <cuda_fp16.h>
#include <cstdint>

#define CB   4
#define CTQ  2048
#define CTK  2048
#define CDV  256
#define CQKD 128
#define CH   8
#define COUT 1024

// 0.25 * log2(e): folded into Q projection so softmax exp becomes exp2.
#define SCALE_Q 0.36067376022224085f

// Scratch (device globals: allocation-free). fp16 payloads.
__device__ __half g_Qc[CB*CTQ*1024];              // 16 MB
__device__ __half g_Kc[CB*CTK*1024];              // 16 MB
__device__ __half g_Vct[(size_t)CB*CDV*CTK];      //  4 MB  V^T compacted [b][dv][key]
__device__ __half g_Qlow[CB*CTQ*CQKD];            //  2 MB (pre-scaled by SCALE_Q)
__device__ __half g_Klowc[CB*CTK*CQKD];           //  2 MB compacted (scatter from proj)
__device__ __half g_Obuf[(size_t)CB*CTQ*CH*CDV];  // 32 MB
__device__ __half g_Wqh[CQKD*1024];
__device__ __half g_Wkh[CQKD*1024];
__device__ __half g_Woh[COUT*CH*CDV];
__device__ int    g_cidx[CB*CTK];
__device__ int    g_pos[CB*CTK];
__device__ int    g_nk[CB];

__device__ __forceinline__ void mma16(float* c, const uint32_t* a, const uint32_t* b){
    asm volatile(
      "mma.sync.aligned.m16n8k16.row.col.f32.f16.f16.f32 "
      "{%0,%1,%2,%3},{%4,%5,%6,%7},{%8,%9},{%0,%1,%2,%3};"
      : "+f"(c[0]), "+f"(c[1]), "+f"(c[2]), "+f"(c[3])
      : "r"(a[0]), "r"(a[1]), "r"(a[2]), "r"(a[3]), "r"(b[0]), "r"(b[1]));
}
__device__ __forceinline__ void ldsm4(uint32_t* r, uint32_t saddr){
    asm volatile("ldmatrix.sync.aligned.m8n8.x4.shared.b16 {%0,%1,%2,%3}, [%4];"
      : "=r"(r[0]), "=r"(r[1]), "=r"(r[2]), "=r"(r[3]) : "r"(saddr));
}
__device__ __forceinline__ uint32_t s2u(const void* p){
    return (uint32_t)__cvta_generic_to_shared(p);
}
__device__ __forceinline__ uint32_t pack2(float x, float y){
    __half2 h = __floats2half2_rn(x, y);
    return *(uint32_t*)&h;
}
// half2{2^x, 2^y} from two fp32 exponents
__device__ __forceinline__ uint32_t ex2h2(float x, float y){
    uint32_t h, r;
    asm("cvt.rn.f16x2.f32 %0, %2, %1;" : "=r"(h) : "f"(x), "f"(y));
    asm("ex2.approx.f16x2 %0, %1;" : "=r"(r) : "r"(h));
    return r;
}
__device__ __forceinline__ void cp16(void* s, const void* g){
    unsigned sa = (unsigned)__cvta_generic_to_shared(s);
    asm volatile("cp.async.cg.shared.global [%0], [%1], 16;" :: "r"(sa), "l"(g));
}
#define CP_COMMIT asm volatile("cp.async.commit_group;")
#define CP_WAIT0  asm volatile("cp.async.wait_group 0;")

// One-shot fp32 -> fp16 conversion of all five tensors (grid-stride).
__global__ void cvt_all_kernel(
    const float4* __restrict__ Q,  const float4* __restrict__ K,
    const float4* __restrict__ Wq, const float4* __restrict__ Wk,
    const float4* __restrict__ Wo,
    uint2* __restrict__ oQ, uint2* __restrict__ oK,
    uint2* __restrict__ oWq, uint2* __restrict__ oWk, uint2* __restrict__ oWo)
{
    const int nQ  = CB*CTQ*1024/4;
    const int nW  = CQKD*1024/4;
    const int nWo = COUT*CH*CDV/4;
    const int total = nQ + nQ + nW + nW + nWo;
    for (int i = blockIdx.x*blockDim.x + threadIdx.x; i < total;
         i += gridDim.x*blockDim.x){
        const float4* s; uint2* d; int j = i;
        if (j < nQ){ s = Q; d = oQ; }
        else if ((j -= nQ) < nQ){ s = K; d = oK; }
        else if ((j -= nQ) < nW){ s = Wq; d = oWq; }
        else if ((j -= nW) < nW){ s = Wk; d = oWk; }
        else { j -= nW; s = Wo; d = oWo; }
        float4 v = s[j];
        uint2 o; o.x = pack2(v.x, v.y); o.y = pack2(v.z, v.w);
        d[j] = o;
    }
}

// Per-batch compaction: cidx (dest->src), pos (src->dest or -1), nk;
// also pre-zeroes the Klowc pad rows (rows nk..align32-1).
__global__ void compact_kernel(const int* __restrict__ mask,
                               int* __restrict__ cidx, int* __restrict__ pos,
                               int* __restrict__ nk, __half* __restrict__ Klowc){
    __shared__ int wsum[32];
    int b = blockIdx.x, t = threadIdx.x;          // 1024 threads, 2 keys each
    int f0 = (mask[b*CTK + 2*t]     == 0);
    int f1 = (mask[b*CTK + 2*t + 1] == 0);
    int c = f0 + f1;
    int lane = t & 31, wid = t >> 5;
    int x = c;
    #pragma unroll
    for (int o = 1; o < 32; o <<= 1){
        int y = __shfl_up_sync(0xffffffffu, x, o);
        if (lane >= o) x += y;
    }
    if (lane == 31) wsum[wid] = x;
    __syncthreads();
    if (wid == 0){
        int y = wsum[lane];
        #pragma unroll
        for (int o = 1; o < 32; o <<= 1){
            int z = __shfl_up_sync(0xffffffffu, y, o);
            if (lane >= o) y += z;
        }
        wsum[lane] = y;
    }
    __syncthreads();
    int excl = x - c + (wid ? wsum[wid-1] : 0);
    pos[b*CTK + 2*t]     = f0 ? excl : -1;
    pos[b*CTK + 2*t + 1] = f1 ? (excl + f0) : -1;
    if (f0) cidx[b*CTK + excl]      = 2*t;
    if (f1) cidx[b*CTK + excl + f0] = 2*t + 1;
    int nkb = wsum[31];
    if (t == 0) nk[b] = nkb;
    int npadrows = ((nkb + 31) & ~31) - nkb;
    for (int idx = t; idx < npadrows*16; idx += 1024){
        int row = nkb + (idx >> 4), col = (idx & 15) * 8;
        *(uint4*)&Klowc[((size_t)b*CTK + row)*CQKD + col] = make_uint4(0,0,0,0);
    }
}

// Fused gather + transpose + fp16 cvt: Vct[b][dv][j] = fp16(V[b][cidx[j]][dv]), 0 pads.
__global__ void gathervt_kernel(const float* __restrict__ V,
                                const int* __restrict__ cidx, const int* __restrict__ nk,
                                __half* __restrict__ Vct){
    __shared__ __half tile[32][33];
    int b = blockIdx.z, kt = blockIdx.x, dt = blockIdx.y;
    int tx = threadIdx.x, ty = threadIdx.y;       // 32 x 8
    int nkb = nk[b];
    int j0 = kt*32;
    if (j0 >= ((nkb + 31) & ~31)) return;
    #pragma unroll
    for (int jj = ty; jj < 32; jj += 8){
        int j = j0 + jj;
        __half hv = __float2half_rn(0.f);
        if (j < nkb)
            hv = __float2half_rn(V[((size_t)b*CTK + cidx[b*CTK + j])*CDV + dt*32 + tx]);
        tile[jj][tx] = hv;
    }
    __syncthreads();
    #pragma unroll
    for (int dd = ty; dd < 32; dd += 8)
        Vct[((size_t)b*CDV + dt*32 + dd)*CTK + j0 + tx] = tile[tx][dd];
}

// C[M][N] = scl*(A[M][K] @ B[N][K]^T + bias[N]).  fp16 m16n8k16 + ldmatrix.
// 128 threads / 4 warps; warp tile (BM/4) x BN; BK=32; OCC blocks/SM.
// SCATTER && z==1: row r stored at compacted row pos[r] (skip if -1).
template<int BM, int BN, bool HALF_OUT, bool SCATTER, int OCC>
__global__ void __launch_bounds__(128,OCC) gemm_kernel(
    const __half* __restrict__ A0, const __half* __restrict__ A1,
    const __half* __restrict__ B0, const __half* __restrict__ B1,
    const float* __restrict__ bias0, const float* __restrict__ bias1,
    void* __restrict__ C0, void* __restrict__ C1, int K,
    float scl0, float scl1, const int* __restrict__ pos)
{
    const __half* A    = blockIdx.z ? A1 : A0;
    const __half* B    = blockIdx.z ? B1 : B0;
    const float*  bias = blockIdx.z ? bias1 : bias0;
    void*         C    = blockIdx.z ? C1 : C0;
    const float   scl  = blockIdx.z ? scl1 : scl0;
    const int N = gridDim.x * BN;

    extern __shared__ char sm[];
    uint32_t* As = (uint32_t*)sm;                 // [2][BM][20] words (80B rows)

    const int m0 = blockIdx.y*BM, n0 = blockIdx.x*BN;
    const int t = threadIdx.x, lane = t & 31, w = t >> 5;
    const int cq = lane & 3;
    constexpr int NF = BN/8;                      // per-warp n fragments
    constexpr int MF = BM/64;                     // per-warp m fragments (16 rows each)

    const uint32_t asb = s2u(As);
    const uint32_t bsb = asb + 2*BM*80;
    const int j8 = lane & 7, mq = lane >> 3;
    const uint32_t aoffL = (uint32_t)(w*(BM/4) + j8 + ((mq&1)<<3))*80 + ((mq>>1)<<4);
    const uint32_t boffL = (uint32_t)(j8 + ((mq>>1)<<3))*80 + ((mq&1)<<4);

    float acc[MF][NF][4];
    #pragma unroll
    for (int i=0;i<MF;i++)
      #pragma unroll
      for (int j=0;j<NF;j++)
        #pragma unroll
        for (int r=0;r<4;r++) acc[i][j][r]=0.f;

    auto load = [&](int s, int k0){
        #pragma unroll
        for (int i=0;i<BM/32;i++){                // A tile BMx32 halves
            int id = t + i*128;
            int r = id>>2, c = (id&3)*8;
            cp16(&As[s*BM*20 + r*20 + c/2], A + (size_t)(m0+r)*K + k0 + c);
        }
        #pragma unroll
        for (int i=0;i<BN/32;i++){                // B tile BNx32 halves
            int id = t + i*128;
            int r = id>>2, c = (id&3)*8;
            cp16((char*)sm + 2*BM*80 + (s*BN*20 + r*20 + c/2)*4,
                 B + (size_t)(n0+r)*K + k0 + c);
        }
    };

    load(0, 0); CP_COMMIT;
    const int NKt = K/32;
    for (int kt = 0; kt < NKt; kt++){
        int s = kt & 1;
        CP_WAIT0;
        __syncthreads();
        if (kt + 1 < NKt){ load(s^1, (kt+1)*32); CP_COMMIT; }
        const uint32_t asS = asb + s*BM*80;
        const uint32_t bsS = bsb + s*BN*80;
        #pragma unroll
        for (int ks = 0; ks < 2; ks++){
            uint32_t a[MF][4];
            #pragma unroll
            for (int mf = 0; mf < MF; mf++)
                ldsm4(a[mf], asS + aoffL + mf*16*80 + ks*32);
            #pragma unroll
            for (int nfp = 0; nfp < NF/2; nfp++){
                uint32_t bb[4];
                ldsm4(bb, bsS + boffL + nfp*16*80 + ks*32);
                #pragma unroll
                for (int mf = 0; mf < MF; mf++){
                    mma16(acc[mf][2*nfp],   a[mf], bb);
                    mma16(acc[mf][2*nfp+1], a[mf], bb+2);
                }
            }
        }
        __syncthreads();
    }

    #pragma unroll
    for (int mf = 0; mf < MF; mf++){
        int r = m0 + w*(BM/4) + mf*16 + (lane>>2);
        size_t ro0 = (size_t)r*N, ro1 = (size_t)(r+8)*N;
        bool st0 = true, st1 = true;
        if (SCATTER && blockIdx.z == 1){
            int bidx = r >> 11;                   // CTK = 2048
            int d0 = pos[r], d1 = pos[r+8];
            st0 = d0 >= 0; st1 = d1 >= 0;
            ro0 = (size_t)(bidx*CTK + (st0 ? d0 : 0))*N;
            ro1 = (size_t)(bidx*CTK + (st1 ? d1 : 0))*N;
        }
        #pragma unroll
        for (int nf = 0; nf < NF; nf++){
            int c = n0 + nf*8 + (cq<<1);
            float b0 = bias[c], b1 = bias[c+1];
            float v0 = (acc[mf][nf][0]+b0)*scl, v1 = (acc[mf][nf][1]+b1)*scl;
            float v2 = (acc[mf][nf][2]+b0)*scl, v3 = (acc[mf][nf][3]+b1)*scl;
            if (HALF_OUT){
                __half* Ch = (__half*)C;
                if (st0) *(uint32_t*)(Ch + ro0 + c) = pack2(v0, v1);
                if (st1) *(uint32_t*)(Ch + ro1 + c) = pack2(v2, v3);
            } else {
                float* Cf = (float*)C;
                *(float2*)(Cf + ro0 + c) = make_float2(v0, v1);
                *(float2*)(Cf + ro1 + c) = make_float2(v2, v3);
            }
        }
    }
}

// ---------- Flash attention over compacted keys (fp16 mma + ldmatrix) ----------
// dv-split: blockIdx.z picks V half (128 dv rows). 128 thr / 4 warps,
// 64 q rows/block, 32 keys/tile. 3 blocks/SM.  (identical to R12)
#define OFF_VS  0                  // [2][128][40]h = 20480 B
#define OFF_KS  20480              // [2][32][24]h  =  3072 B
#define OFF_PS  23552              // [64][40]h     =  5120 B (Q staged here pre-loop)
#define OFF_LI  28672              // [64]f         =   256 B
#define FLASH_SMEM 28928

__device__ __forceinline__ void flash_load(char* sm, int s, int key0,
    const __half* Vtb, const __half* Kl, int t)
{
    char* VsB = sm + OFF_VS + s*10240;
    #pragma unroll
    for (int i = 0; i < 4; i++){                  // 128 dv rows x 32 keys (64B)
        int id = t + i*128;
        int dv = id>>2, c = (id&3)*8;             // halves
        cp16(VsB + dv*80 + c*2, Vtb + (size_t)dv*CTK + key0 + c);
    }
    if (t < 64){                                  // K tile 32x16 halves
        int r = t>>1, c = (t&1)*8;
        cp16(sm + OFF_KS + s*1536 + r*48 + c*2, Kl + (size_t)(key0 + r)*CQKD + c);
    }
}

__global__ void __launch_bounds__(128,3) flash_kernel(const int* __restrict__ nkarr)
{
    extern __shared__ char sm[];
    uint32_t* Ks  = (uint32_t*)(sm + OFF_KS);     // row stride 12 words
    uint32_t* Ps  = (uint32_t*)(sm + OFF_PS);     // row stride 20 words
    float*    lInv= (float*)   (sm + OFF_LI);

    const int t = threadIdx.x, lane = t & 31, w = t >> 5;
    const int cq = lane & 3;
    const int q0 = blockIdx.x * 64;
    const int b  = blockIdx.y >> 3, h = blockIdx.y & 7;
    const int z  = blockIdx.z;                    // dv half

    const int nkb = __ldg(&nkarr[b]);
    const int NT  = (nkb + 31) >> 5;
    const float npad = (float)(NT*32 - nkb);

    const __half* Vtb = g_Vct   + (size_t)b*CDV*CTK + (size_t)(z*128)*CTK;
    const __half* Kl  = g_Klowc + (size_t)b*CTK*CQKD + h*16;

    flash_load(sm, 0, 0, Vtb, Kl, t);
    CP_COMMIT;

    // Stage Q tile (64x16 halves) into Ps region (stride 12 words).
    {
        int r = t>>1;
        const uint4* src = (const uint4*)(g_Qlow + (size_t)(b*CTQ + q0 + r)*CQKD + h*16);
        *(uint4*)&Ps[r*12 + (t&1)*4] = src[t&1];
    }
    __syncthreads();
    uint32_t qa[4];
    {
        int r = w*16 + (lane>>2);
        qa[0] = Ps[r*12 + cq];       qa[1] = Ps[(r+8)*12 + cq];
        qa[2] = Ps[r*12 + cq + 4];   qa[3] = Ps[(r+8)*12 + cq + 4];
    }

    const int wm = w >> 1, wn = w & 1;            // P@V map: rows wm*32, cols wn*64
    const uint32_t vsb = s2u(sm + OFF_VS);
    const uint32_t psb = s2u(sm + OFF_PS);
    const int j8 = lane & 7, mq = lane >> 3;
    const uint32_t aoffL = (uint32_t)(wm*32 + j8 + ((mq&1)<<3))*80 + ((mq>>1)<<4);
    const uint32_t boffL = (uint32_t)(wn*64 + j8 + ((mq>>1)<<3))*80 + ((mq&1)<<4);

    float acc[2][8][4];
    #pragma unroll
    for (int i=0;i<2;i++)
      #pragma unroll
      for (int j=0;j<8;j++)
        #pragma unroll
        for (int r=0;r<4;r++) acc[i][j][r]=0.f;
    float accL[2][4];                             // ones-MMA row-sum accumulators
    #pragma unroll
    for (int i=0;i<2;i++)
      #pragma unroll
      for (int r=0;r<4;r++) accL[i][r]=0.f;
    const uint32_t ones2[2] = {0x3C003C00u, 0x3C003C00u};

    for (int kt = 0; kt < NT; kt++){
        int s = kt & 1;
        CP_WAIT0;
        __syncthreads();
        if (kt + 1 < NT){ flash_load(sm, s^1, (kt+1)*32, Vtb, Kl, t); CP_COMMIT; }

        // --- scores (exp2 units): rows w*16..+15, 32 cols; 4 mma ---
        {
            const uint32_t* KsS = Ks + s*384;
            int r = w*16 + (lane>>2);
            #pragma unroll
            for (int j = 0; j < 4; j++){
                float c0[4] = {0.f,0.f,0.f,0.f};
                int n = j*8 + (lane>>2);
                uint32_t bb[2];
                bb[0] = KsS[n*12 + cq];
                bb[1] = KsS[n*12 + cq + 4];
                mma16(c0, qa, bb);
                Ps[r*20 + j*4 + cq]     = ex2h2(c0[0], c0[1]);
                Ps[(r+8)*20 + j*4 + cq] = ex2h2(c0[2], c0[3]);
            }
        }
        __syncthreads();

        // --- P(64x32) @ V(32x128 half) + ones-MMA row sums ---
        {
            const uint32_t vsS = vsb + s*10240;
            #pragma unroll
            for (int ks = 0; ks < 2; ks++){
                uint32_t a[2][4];
                ldsm4(a[0], psb + aoffL + ks*32);
                ldsm4(a[1], psb + aoffL + 16*80 + ks*32);
                mma16(accL[0], a[0], ones2);
                mma16(accL[1], a[1], ones2);
                #pragma unroll
                for (int nfp = 0; nfp < 4; nfp++){
                    uint32_t bb[4];
                    ldsm4(bb, vsS + boffL + nfp*16*80 + ks*32);
                    mma16(acc[0][2*nfp],   a[0], bb);
                    mma16(acc[1][2*nfp],   a[1], bb);
                    mma16(acc[0][2*nfp+1], a[0], bb+2);
                    mma16(acc[1][2*nfp+1], a[1], bb+2);
                }
            }
        }
    }

    // Row-sum inverses from accL (wn=0 writes; identical in both z blocks).
    if (wn == 0 && cq == 0){
        #pragma unroll
        for (int mf = 0; mf < 2; mf++){
            int r = wm*32 + mf*16 + (lane>>2);
            lInv[r]     = 1.f / (accL[mf][0] - npad);
            lInv[r + 8] = 1.f / (accL[mf][2] - npad);
        }
    }
    __syncthreads();

    #pragma unroll
    for (int mf = 0; mf < 2; mf++){
        int rl = wm*32 + mf*16 + (lane>>2);
        float i0 = lInv[rl], i1 = lInv[rl+8];
        __half* row0 = g_Obuf + (size_t)(b*CTQ + q0 + rl)    *(CH*CDV) + h*CDV;
        __half* row1 = g_Obuf + (size_t)(b*CTQ + q0 + rl + 8)*(CH*CDV) + h*CDV;
        #pragma unroll
        for (int nf = 0; nf < 8; nf++){
            int c2 = z*128 + wn*64 + nf*8 + (cq<<1);
            *(uint32_t*)(row0 + c2) = pack2(acc[mf][nf][0]*i0, acc[mf][nf][1]*i0);
            *(uint32_t*)(row1 + c2) = pack2(acc[mf][nf][2]*i1, acc[mf][nf][3]*i1);
        }
    }
}

static const int GEMM_SMEM_64_64  = (2*64*20  + 2*64*20)*4;   // 20480
static const int GEMM_SMEM_128_128= (2*128*20 + 2*128*20)*4;  // 40960

extern "C" void kernel_launch(void* const* d_in, const int* in_sizes, int n_in,
                              void* d_out, int out_size)
{
    const float* Q    = (const float*)d_in[0];
    const float* K    = (const float*)d_in[1];
    const float* V    = (const float*)d_in[2];
    const int*   mask = (const int*)  d_in[3];
    const float* Wq   = (const float*)d_in[4];
    const float* bq   = (const float*)d_in[5];
    const float* Wk   = (const float*)d_in[6];
    const float* bk   = (const float*)d_in[7];
    const float* Wo   = (const float*)d_in[8];
    const float* bo   = (const float*)d_in[9];
    float* out = (float*)d_out;

    __half *dQc,*dKc,*dVct,*dQlow,*dKlowc,*dObuf,*dWqh,*dWkh,*dWoh;
    int *dCidx,*dPos,*dNk;
    cudaGetSymbolAddress((void**)&dQc,    g_Qc);
    cudaGetSymbolAddress((void**)&dKc,    g_Kc);
    cudaGetSymbolAddress((void**)&dVct,   g_Vct);
    cudaGetSymbolAddress((void**)&dQlow,  g_Qlow);
    cudaGetSymbolAddress((void**)&dKlowc, g_Klowc);
    cudaGetSymbolAddress((void**)&dObuf,  g_Obuf);
    cudaGetSymbolAddress((void**)&dWqh,   g_Wqh);
    cudaGetSymbolAddress((void**)&dWkh,   g_Wkh);
    cudaGetSymbolAddress((void**)&dWoh,   g_Woh);
    cudaGetSymbolAddress((void**)&dCidx,  g_cidx);
    cudaGetSymbolAddress((void**)&dPos,   g_pos);
    cudaGetSymbolAddress((void**)&dNk,    g_nk);

    cudaFuncSetAttribute((const void*)gemm_kernel<64,64,true,true,4>,
                         cudaFuncAttributeMaxDynamicSharedMemorySize, GEMM_SMEM_64_64);
    cudaFuncSetAttribute((const void*)gemm_kernel<128,128,false,false,2>,
                         cudaFuncAttributeMaxDynamicSharedMemorySize, GEMM_SMEM_128_128);
    cudaFuncSetAttribute((const void*)flash_kernel,
                         cudaFuncAttributeMaxDynamicSharedMemorySize, FLASH_SMEM);

    // One merged fp16 conversion for Q, K, Wq, Wk, Wo
    cvt_all_kernel<<<2048,256>>>(
        (const float4*)Q, (const float4*)K,
        (const float4*)Wq, (const float4*)Wk, (const float4*)Wo,
        (uint2*)dQc, (uint2*)dKc, (uint2*)dWqh, (uint2*)dWkh, (uint2*)dWoh);

    // Mask compaction + V gather/transpose
    compact_kernel<<<CB, 1024>>>(mask, dCidx, dPos, dNk, dKlowc);
    gathervt_kernel<<<dim3(CTK/32, CDV/32, CB), dim3(32,8)>>>(V, dCidx, dNk, dVct);

    // Fused Q/K projections: BM=64 -> grid 512 blocks, OCC=4
    gemm_kernel<64,64,true,true,4><<<dim3(2, 128, 2), 128, GEMM_SMEM_64_64>>>(
        dQc, dKc, dWqh, dWkh, bq, bk, dQlow, dKlowc, 1024, SCALE_Q, 1.0f, dPos);

    // Flash: dv-split (z in {0,1}), 3 blocks/SM  (identical to R12)
    flash_kernel<<<dim3(CTQ/64, CB*CH, 2), 128, FLASH_SMEM>>>(dNk);

    // Final GEMM: proven R12 shape (BM=128, 128 thr, OCC=2)
    gemm_kernel<128,128,false,false,2><<<dim3(8, 64, 1), 128, GEMM_SMEM_128_128>>>(
        dObuf, dObuf, dWoh, dWoh, bo, bo, out, out, 2048, 1.0f, 1.0f, nullptr);
}

// round 15
// speedup vs baseline: 1.6996x; 1.0901x over previous
#include <cuda_runtime.h>
#include <cuda_fp16.h>
#include <cstdint>

#define CB   4
#define CTQ  2048
#define CTK  2048
#define CDV  256
#define CQKD 128
#define CH   8
#define COUT 1024

// 0.25 * log2(e): folded into Q projection so softmax exp becomes exp2.
#define SCALE_Q 0.36067376022224085f

// Scratch (device globals: allocation-free). fp16 payloads.
__device__ __half g_Qc[CB*CTQ*1024];              // 16 MB
__device__ __half g_Kc[CB*CTK*1024];              // 16 MB
__device__ __half g_Vct[(size_t)CB*CDV*CTK];      //  4 MB  V^T compacted [b][dv][key]
__device__ __half g_Qlow[CB*CTQ*CQKD];            //  2 MB (pre-scaled by SCALE_Q)
__device__ __half g_Klowc[CB*CTK*CQKD];           //  2 MB compacted (scatter from proj)
__device__ __half g_Obuf[(size_t)CB*CTQ*CH*CDV];  // 32 MB
__device__ __half g_Wqh[CQKD*1024];
__device__ __half g_Wkh[CQKD*1024];
__device__ __half g_Woh[COUT*CH*CDV];
__device__ int    g_cidx[CB*CTK];
__device__ int    g_pos[CB*CTK];
__device__ int    g_nk[CB];

__device__ __forceinline__ void mma16(float* c, const uint32_t* a, const uint32_t* b){
    asm volatile(
      "mma.sync.aligned.m16n8k16.row.col.f32.f16.f16.f32 "
      "{%0,%1,%2,%3},{%4,%5,%6,%7},{%8,%9},{%0,%1,%2,%3};"
      : "+f"(c[0]), "+f"(c[1]), "+f"(c[2]), "+f"(c[3])
      : "r"(a[0]), "r"(a[1]), "r"(a[2]), "r"(a[3]), "r"(b[0]), "r"(b[1]));
}
__device__ __forceinline__ void ldsm4(uint32_t* r, uint32_t saddr){
    asm volatile("ldmatrix.sync.aligned.m8n8.x4.shared.b16 {%0,%1,%2,%3}, [%4];"
      : "=r"(r[0]), "=r"(r[1]), "=r"(r[2]), "=r"(r[3]) : "r"(saddr));
}
__device__ __forceinline__ uint32_t s2u(const void* p){
    return (uint32_t)__cvta_generic_to_shared(p);
}
__device__ __forceinline__ uint32_t pack2(float x, float y){
    __half2 h = __floats2half2_rn(x, y);
    return *(uint32_t*)&h;
}
// half2{2^x, 2^y} from two fp32 exponents
__device__ __forceinline__ uint32_t ex2h2(float x, float y){
    uint32_t h, r;
    asm("cvt.rn.f16x2.f32 %0, %2, %1;" : "=r"(h) : "f"(x), "f"(y));
    asm("ex2.approx.f16x2 %0, %1;" : "=r"(r) : "r"(h));
    return r;
}
__device__ __forceinline__ void cp16(void* s, const void* g){
    unsigned sa = (unsigned)__cvta_generic_to_shared(s);
    asm volatile("cp.async.cg.shared.global [%0], [%1], 16;" :: "r"(sa), "l"(g));
}
#define CP_COMMIT asm volatile("cp.async.commit_group;")
#define CP_WAIT0  asm volatile("cp.async.wait_group 0;")

// fp32 -> fp16: Q, K, Wq, Wk (grid-stride over all four).
__global__ void cvtQK_kernel(
    const float4* __restrict__ Q,  const float4* __restrict__ K,
    const float4* __restrict__ Wq, const float4* __restrict__ Wk,
    uint2* __restrict__ oQ, uint2* __restrict__ oK,
    uint2* __restrict__ oWq, uint2* __restrict__ oWk)
{
    const int nQ  = CB*CTQ*1024/4;
    const int nW  = CQKD*1024/4;
    const int total = nQ + nQ + nW + nW;
    for (int i = blockIdx.x*blockDim.x + threadIdx.x; i < total;
         i += gridDim.x*blockDim.x){
        const float4* s; uint2* d; int j = i;
        if (j < nQ){ s = Q; d = oQ; }
        else if ((j -= nQ) < nQ){ s = K; d = oK; }
        else if ((j -= nQ) < nW){ s = Wq; d = oWq; }
        else { j -= nW; s = Wk; d = oWk; }
        float4 v = s[j];
        uint2 o; o.x = pack2(v.x, v.y); o.y = pack2(v.z, v.w);
        d[j] = o;
    }
}

// fp32 -> fp16: Wo alone.
__global__ void cvtWo_kernel(const float4* __restrict__ Wo, uint2* __restrict__ oWo){
    const int n = COUT*CH*CDV/4;
    for (int i = blockIdx.x*blockDim.x + threadIdx.x; i < n;
         i += gridDim.x*blockDim.x){
        float4 v = Wo[i];
        uint2 o; o.x = pack2(v.x, v.y); o.y = pack2(v.z, v.w);
        oWo[i] = o;
    }
}

// Per-batch compaction: cidx (dest->src), pos (src->dest or -1), nk;
// also pre-zeroes the Klowc pad rows (rows nk..align32-1).
__global__ void compact_kernel(const int* __restrict__ mask,
                               int* __restrict__ cidx, int* __restrict__ pos,
                               int* __restrict__ nk, __half* __restrict__ Klowc){
    __shared__ int wsum[32];
    int b = blockIdx.x, t = threadIdx.x;          // 1024 threads, 2 keys each
    int f0 = (mask[b*CTK + 2*t]     == 0);
    int f1 = (mask[b*CTK + 2*t + 1] == 0);
    int c = f0 + f1;
    int lane = t & 31, wid = t >> 5;
    int x = c;
    #pragma unroll
    for (int o = 1; o < 32; o <<= 1){
        int y = __shfl_up_sync(0xffffffffu, x, o);
        if (lane >= o) x += y;
    }
    if (lane == 31) wsum[wid] = x;
    __syncthreads();
    if (wid == 0){
        int y = wsum[lane];
        #pragma unroll
        for (int o = 1; o < 32; o <<= 1){
            int z = __shfl_up_sync(0xffffffffu, y, o);
            if (lane >= o) y += z;
        }
        wsum[lane] = y;
    }
    __syncthreads();
    int excl = x - c + (wid ? wsum[wid-1] : 0);
    pos[b*CTK + 2*t]     = f0 ? excl : -1;
    pos[b*CTK + 2*t + 1] = f1 ? (excl + f0) : -1;
    if (f0) cidx[b*CTK + excl]      = 2*t;
    if (f1) cidx[b*CTK + excl + f0] = 2*t + 1;
    int nkb = wsum[31];
    if (t == 0) nk[b] = nkb;
    int npadrows = ((nkb + 31) & ~31) - nkb;
    for (int idx = t; idx < npadrows*16; idx += 1024){
        int row = nkb + (idx >> 4), col = (idx & 15) * 8;
        *(uint4*)&Klowc[((size_t)b*CTK + row)*CQKD + col] = make_uint4(0,0,0,0);
    }
}

// Fused gather + transpose + fp16 cvt: Vct[b][dv][j] = fp16(V[b][cidx[j]][dv]), 0 pads.
__global__ void gathervt_kernel(const float* __restrict__ V,
                                const int* __restrict__ cidx, const int* __restrict__ nk,
                                __half* __restrict__ Vct){
    __shared__ __half tile[32][33];
    int b = blockIdx.z, kt = blockIdx.x, dt = blockIdx.y;
    int tx = threadIdx.x, ty = threadIdx.y;       // 32 x 8
    int nkb = nk[b];
    int j0 = kt*32;
    if (j0 >= ((nkb + 31) & ~31)) return;
    #pragma unroll
    for (int jj = ty; jj < 32; jj += 8){
        int j = j0 + jj;
        __half hv = __float2half_rn(0.f);
        if (j < nkb)
            hv = __float2half_rn(V[((size_t)b*CTK + cidx[b*CTK + j])*CDV + dt*32 + tx]);
        tile[jj][tx] = hv;
    }
    __syncthreads();
    #pragma unroll
    for (int dd = ty; dd < 32; dd += 8)
        Vct[((size_t)b*CDV + dt*32 + dd)*CTK + j0 + tx] = tile[tx][dd];
}

// C[M][N] = scl*(A[M][K] @ B[N][K]^T + bias[N]).  fp16 m16n8k16 + ldmatrix.
// 128 threads / 4 warps; warp tile (BM/4) x BN; BK=32; OCC blocks/SM.
// SCATTER && z==1: row r stored at compacted row pos[r] (skip if -1).
template<int BM, int BN, bool HALF_OUT, bool SCATTER, int OCC>
__global__ void __launch_bounds__(128,OCC) gemm_kernel(
    const __half* __restrict__ A0, const __half* __restrict__ A1,
    const __half* __restrict__ B0, const __half* __restrict__ B1,
    const float* __restrict__ bias0, const float* __restrict__ bias1,
    void* __restrict__ C0, void* __restrict__ C1, int K,
    float scl0, float scl1, const int* __restrict__ pos)
{
    const __half* A    = blockIdx.z ? A1 : A0;
    const __half* B    = blockIdx.z ? B1 : B0;
    const float*  bias = blockIdx.z ? bias1 : bias0;
    void*         C    = blockIdx.z ? C1 : C0;
    const float   scl  = blockIdx.z ? scl1 : scl0;
    const int N = gridDim.x * BN;

    extern __shared__ char sm[];
    uint32_t* As = (uint32_t*)sm;                 // [2][BM][20] words (80B rows)

    const int m0 = blockIdx.y*BM, n0 = blockIdx.x*BN;
    const int t = threadIdx.x, lane = t & 31, w = t >> 5;
    const int cq = lane & 3;
    constexpr int NF = BN/8;
    constexpr int MF = BM/64;

    const uint32_t asb = s2u(As);
    const uint32_t bsb = asb + 2*BM*80;
    const int j8 = lane & 7, mq = lane >> 3;
    const uint32_t aoffL = (uint32_t)(w*(BM/4) + j8 + ((mq&1)<<3))*80 + ((mq>>1)<<4);
    const uint32_t boffL = (uint32_t)(j8 + ((mq>>1)<<3))*80 + ((mq&1)<<4);

    float acc[MF][NF][4];
    #pragma unroll
    for (int i=0;i<MF;i++)
      #pragma unroll
      for (int j=0;j<NF;j++)
        #pragma unroll
        for (int r=0;r<4;r++) acc[i][j][r]=0.f;

    auto load = [&](int s, int k0){
        #pragma unroll
        for (int i=0;i<BM/32;i++){                // A tile BMx32 halves
            int id = t + i*128;
            int r = id>>2, c = (id&3)*8;
            cp16(&As[s*BM*20 + r*20 + c/2], A + (size_t)(m0+r)*K + k0 + c);
        }
        #pragma unroll
        for (int i=0;i<BN/32;i++){                // B tile BNx32 halves
            int id = t + i*128;
            int r = id>>2, c = (id&3)*8;
            cp16((char*)sm + 2*BM*80 + (s*BN*20 + r*20 + c/2)*4,
                 B + (size_t)(n0+r)*K + k0 + c);
        }
    };

    load(0, 0); CP_COMMIT;
    const int NKt = K/32;
    for (int kt = 0; kt < NKt; kt++){
        int s = kt & 1;
        CP_WAIT0;
        __syncthreads();
        if (kt + 1 < NKt){ load(s^1, (kt+1)*32); CP_COMMIT; }
        const uint32_t asS = asb + s*BM*80;
        const uint32_t bsS = bsb + s*BN*80;
        #pragma unroll
        for (int ks = 0; ks < 2; ks++){
            uint32_t a[MF][4];
            #pragma unroll
            for (int mf = 0; mf < MF; mf++)
                ldsm4(a[mf], asS + aoffL + mf*16*80 + ks*32);
            #pragma unroll
            for (int nfp = 0; nfp < NF/2; nfp++){
                uint32_t bb[4];
                ldsm4(bb, bsS + boffL + nfp*16*80 + ks*32);
                #pragma unroll
                for (int mf = 0; mf < MF; mf++){
                    mma16(acc[mf][2*nfp],   a[mf], bb);
                    mma16(acc[mf][2*nfp+1], a[mf], bb+2);
                }
            }
        }
        __syncthreads();
    }

    #pragma unroll
    for (int mf = 0; mf < MF; mf++){
        int r = m0 + w*(BM/4) + mf*16 + (lane>>2);
        size_t ro0 = (size_t)r*N, ro1 = (size_t)(r+8)*N;
        bool st0 = true, st1 = true;
        if (SCATTER && blockIdx.z == 1){
            int bidx = r >> 11;                   // CTK = 2048
            int d0 = pos[r], d1 = pos[r+8];
            st0 = d0 >= 0; st1 = d1 >= 0;
            ro0 = (size_t)(bidx*CTK + (st0 ? d0 : 0))*N;
            ro1 = (size_t)(bidx*CTK + (st1 ? d1 : 0))*N;
        }
        #pragma unroll
        for (int nf = 0; nf < NF; nf++){
            int c = n0 + nf*8 + (cq<<1);
            float b0 = bias[c], b1 = bias[c+1];
            float v0 = (acc[mf][nf][0]+b0)*scl, v1 = (acc[mf][nf][1]+b1)*scl;
            float v2 = (acc[mf][nf][2]+b0)*scl, v3 = (acc[mf][nf][3]+b1)*scl;
            if (HALF_OUT){
                __half* Ch = (__half*)C;
                if (st0) *(uint32_t*)(Ch + ro0 + c) = pack2(v0, v1);
                if (st1) *(uint32_t*)(Ch + ro1 + c) = pack2(v2, v3);
            } else {
                float* Cf = (float*)C;
                *(float2*)(Cf + ro0 + c) = make_float2(v0, v1);
                *(float2*)(Cf + ro1 + c) = make_float2(v2, v3);
            }
        }
    }
}

// ---------- Flash attention over compacted keys (fp16 mma + ldmatrix) ----------
// dv-split: blockIdx.z picks V half (128 dv rows). 128 thr / 4 warps,
// 64 q rows/block, 32 keys/tile. 4 blocks/SM.
#define OFF_VS  0                  // [2][128][40]h = 20480 B
#define OFF_KS  20480              // [2][32][24]h  =  3072 B
#define OFF_PS  23552              // [64][40]h     =  5120 B (Q staged here pre-loop)
#define OFF_LI  28672              // [64]f         =   256 B
#define FLASH_SMEM 28928

__device__ __forceinline__ void flash_load(char* sm, int s, int key0,
    const __half* Vtb, const __half* Kl, int t)
{
    char* VsB = sm + OFF_VS + s*10240;
    #pragma unroll
    for (int i = 0; i < 4; i++){                  // 128 dv rows x 32 keys (64B)
        int id = t + i*128;
        int dv = id>>2, c = (id&3)*8;             // halves
        cp16(VsB + dv*80 + c*2, Vtb + (size_t)dv*CTK + key0 + c);
    }
    if (t < 64){                                  // K tile 32x16 halves
        int r = t>>1, c = (t&1)*8;
        cp16(sm + OFF_KS + s*1536 + r*48 + c*2, Kl + (size_t)(key0 + r)*CQKD + c);
    }
}

__global__ void __launch_bounds__(128,4) flash_kernel(const int* __restrict__ nkarr)
{
    extern __shared__ char sm[];
    uint32_t* Ks  = (uint32_t*)(sm + OFF_KS);     // row stride 12 words
    uint32_t* Ps  = (uint32_t*)(sm + OFF_PS);     // row stride 20 words
    float*    lInv= (float*)   (sm + OFF_LI);

    const int t = threadIdx.x, lane = t & 31, w = t >> 5;
    const int cq = lane & 3;
    const int q0 = blockIdx.x * 64;
    const int b  = blockIdx.y >> 3, h = blockIdx.y & 7;
    const int z  = blockIdx.z;                    // dv half

    const int nkb = __ldg(&nkarr[b]);
    const int NT  = (nkb + 31) >> 5;
    const float npad = (float)(NT*32 - nkb);

    const __half* Vtb = g_Vct   + (size_t)b*CDV*CTK + (size_t)(z*128)*CTK;
    const __half* Kl  = g_Klowc + (size_t)b*CTK*CQKD + h*16;

    flash_load(sm, 0, 0, Vtb, Kl, t);
    CP_COMMIT;

    // Stage Q tile (64x16 halves) into Ps region (stride 12 words).
    {
        int r = t>>1;
        const uint4* src = (const uint4*)(g_Qlow + (size_t)(b*CTQ + q0 + r)*CQKD + h*16);
        *(uint4*)&Ps[r*12 + (t&1)*4] = src[t&1];
    }
    __syncthreads();
    uint32_t qa[4];
    {
        int r = w*16 + (lane>>2);
        qa[0] = Ps[r*12 + cq];       qa[1] = Ps[(r+8)*12 + cq];
        qa[2] = Ps[r*12 + cq + 4];   qa[3] = Ps[(r+8)*12 + cq + 4];
    }

    const int wm = w >> 1, wn = w & 1;            // P@V map: rows wm*32, cols wn*64
    const uint32_t vsb = s2u(sm + OFF_VS);
    const uint32_t psb = s2u(sm + OFF_PS);
    const int j8 = lane & 7, mq = lane >> 3;
    const uint32_t aoffL = (uint32_t)(wm*32 + j8 + ((mq&1)<<3))*80 + ((mq>>1)<<4);
    const uint32_t boffL = (uint32_t)(wn*64 + j8 + ((mq>>1)<<3))*80 + ((mq&1)<<4);

    float acc[2][8][4];
    #pragma unroll
    for (int i=0;i<2;i++)
      #pragma unroll
      for (int j=0;j<8;j++)
        #pragma unroll
        for (int r=0;r<4;r++) acc[i][j][r]=0.f;
    float accL[2][4];                             // ones-MMA row-sum accumulators
    #pragma unroll
    for (int i=0;i<2;i++)
      #pragma unroll
      for (int r=0;r<4;r++) accL[i][r]=0.f;
    const uint32_t ones2[2] = {0x3C003C00u, 0x3C003C00u};

    for (int kt = 0; kt < NT; kt++){
        int s = kt & 1;
        CP_WAIT0;
        __syncthreads();
        if (kt + 1 < NT){ flash_load(sm, s^1, (kt+1)*32, Vtb, Kl, t); CP_COMMIT; }

        // --- scores (exp2 units): rows w*16..+15, 32 cols; 4 mma ---
        {
            const uint32_t* KsS = Ks + s*384;
            int r = w*16 + (lane>>2);
            #pragma unroll
            for (int j = 0; j < 4; j++){
                float c0[4] = {0.f,0.f,0.f,0.f};
                int n = j*8 + (lane>>2);
                uint32_t bb[2];
                bb[0] = KsS[n*12 + cq];
                bb[1] = KsS[n*12 + cq + 4];
                mma16(c0, qa, bb);
                Ps[r*20 + j*4 + cq]     = ex2h2(c0[0], c0[1]);
                Ps[(r+8)*20 + j*4 + cq] = ex2h2(c0[2], c0[3]);
            }
        }
        __syncthreads();

        // --- P(64x32) @ V(32x128 half) + ones-MMA row sums ---
        {
            const uint32_t vsS = vsb + s*10240;
            #pragma unroll
            for (int ks = 0; ks < 2; ks++){
                uint32_t a[2][4];
                ldsm4(a[0], psb + aoffL + ks*32);
                ldsm4(a[1], psb + aoffL + 16*80 + ks*32);
                mma16(accL[0], a[0], ones2);
                mma16(accL[1], a[1], ones2);
                #pragma unroll
                for (int nfp = 0; nfp < 4; nfp++){
                    uint32_t bb[4];
                    ldsm4(bb, vsS + boffL + nfp*16*80 + ks*32);
                    mma16(acc[0][2*nfp],   a[0], bb);
                    mma16(acc[1][2*nfp],   a[1], bb);
                    mma16(acc[0][2*nfp+1], a[0], bb+2);
                    mma16(acc[1][2*nfp+1], a[1], bb+2);
                }
            }
        }
    }

    // Row-sum inverses from accL (wn=0 writes; identical in both z blocks).
    if (wn == 0 && cq == 0){
        #pragma unroll
        for (int mf = 0; mf < 2; mf++){
            int r = wm*32 + mf*16 + (lane>>2);
            lInv[r]     = 1.f / (accL[mf][0] - npad);
            lInv[r + 8] = 1.f / (accL[mf][2] - npad);
        }
    }
    __syncthreads();

    #pragma unroll
    for (int mf = 0; mf < 2; mf++){
        int rl = wm*32 + mf*16 + (lane>>2);
        float i0 = lInv[rl], i1 = lInv[rl+8];
        __half* row0 = g_Obuf + (size_t)(b*CTQ + q0 + rl)    *(CH*CDV) + h*CDV;
        __half* row1 = g_Obuf + (size_t)(b*CTQ + q0 + rl + 8)*(CH*CDV) + h*CDV;
        #pragma unroll
        for (int nf = 0; nf < 8; nf++){
            int c2 = z*128 + wn*64 + nf*8 + (cq<<1);
            *(uint32_t*)(row0 + c2) = pack2(acc[mf][nf][0]*i0, acc[mf][nf][1]*i0);
            *(uint32_t*)(row1 + c2) = pack2(acc[mf][nf][2]*i1, acc[mf][nf][3]*i1);
        }
    }
}

static const int GEMM_SMEM_128_64 = (2*128*20 + 2*64*20)*4;   // 30720
static const int GEMM_SMEM_128_128= (2*128*20 + 2*128*20)*4;  // 40960

extern "C" void kernel_launch(void* const* d_in, const int* in_sizes, int n_in,
                              void* d_out, int out_size)
{
    const float* Q    = (const float*)d_in[0];
    const float* K    = (const float*)d_in[1];
    const float* V    = (const float*)d_in[2];
    const int*   mask = (const int*)  d_in[3];
    const float* Wq   = (const float*)d_in[4];
    const float* bq   = (const float*)d_in[5];
    const float* Wk   = (const float*)d_in[6];
    const float* bk   = (const float*)d_in[7];
    const float* Wo   = (const float*)d_in[8];
    const float* bo   = (const float*)d_in[9];
    float* out = (float*)d_out;

    __half *dQc,*dKc,*dVct,*dQlow,*dKlowc,*dObuf,*dWqh,*dWkh,*dWoh;
    int *dCidx,*dPos,*dNk;
    cudaGetSymbolAddress((void**)&dQc,    g_Qc);
    cudaGetSymbolAddress((void**)&dKc,    g_Kc);
    cudaGetSymbolAddress((void**)&dVct,   g_Vct);
    cudaGetSymbolAddress((void**)&dQlow,  g_Qlow);
    cudaGetSymbolAddress((void**)&dKlowc, g_Klowc);
    cudaGetSymbolAddress((void**)&dObuf,  g_Obuf);
    cudaGetSymbolAddress((void**)&dWqh,   g_Wqh);
    cudaGetSymbolAddress((void**)&dWkh,   g_Wkh);
    cudaGetSymbolAddress((void**)&dWoh,   g_Woh);
    cudaGetSymbolAddress((void**)&dCidx,  g_cidx);
    cudaGetSymbolAddress((void**)&dPos,   g_pos);
    cudaGetSymbolAddress((void**)&dNk,    g_nk);

    cudaFuncSetAttribute((const void*)gemm_kernel<128,64,true,true,3>,
                         cudaFuncAttributeMaxDynamicSharedMemorySize, GEMM_SMEM_128_64);
    cudaFuncSetAttribute((const void*)gemm_kernel<128,128,false,false,2>,
                         cudaFuncAttributeMaxDynamicSharedMemorySize, GEMM_SMEM_128_128);
    cudaFuncSetAttribute((const void*)flash_kernel,
                         cudaFuncAttributeMaxDynamicSharedMemorySize, FLASH_SMEM);

    // Side stream + events (created once; creation happens outside capture on
    // the first, uncaptured, correctness call; replays never run host code).
    static cudaStream_t sB = nullptr;
    static cudaEvent_t  eFork = nullptr, eComp = nullptr, eGav = nullptr, eWo = nullptr;
    if (!sB){
        cudaStreamCreateWithFlags(&sB, cudaStreamNonBlocking);
        cudaEventCreateWithFlags(&eFork, cudaEventDisableTiming);
        cudaEventCreateWithFlags(&eComp, cudaEventDisableTiming);
        cudaEventCreateWithFlags(&eGav,  cudaEventDisableTiming);
        cudaEventCreateWithFlags(&eWo,   cudaEventDisableTiming);
    }

    // Fork side branch from the main (default) stream.
    cudaEventRecord(eFork, 0);
    cudaStreamWaitEvent(sB, eFork, 0);

    // Branch B: compact -> gathervt -> cvt(Wo)
    compact_kernel<<<CB, 1024, 0, sB>>>(mask, dCidx, dPos, dNk, dKlowc);
    cudaEventRecord(eComp, sB);
    gathervt_kernel<<<dim3(CTK/32, CDV/32, CB), dim3(32,8), 0, sB>>>(V, dCidx, dNk, dVct);
    cudaEventRecord(eGav, sB);
    cvtWo_kernel<<<512, 256, 0, sB>>>((const float4*)Wo, (uint2*)dWoh);
    cudaEventRecord(eWo, sB);

    // Branch A (default stream): cvt(Q,K,Wq,Wk)
    cvtQK_kernel<<<2048,256>>>(
        (const float4*)Q, (const float4*)K, (const float4*)Wq, (const float4*)Wk,
        (uint2*)dQc, (uint2*)dKc, (uint2*)dWqh, (uint2*)dWkh);

    // Projections need pos (compact). BM=128, OCC=3 (R12 shape).
    cudaStreamWaitEvent(0, eComp, 0);
    gemm_kernel<128,64,true,true,3><<<dim3(2, 64, 2), 128, GEMM_SMEM_128_64>>>(
        dQc, dKc, dWqh, dWkh, bq, bk, dQlow, dKlowc, 1024, SCALE_Q, 1.0f, dPos);

    // Flash needs Vct (gathervt). dv-split, 4 blocks/SM.
    cudaStreamWaitEvent(0, eGav, 0);
    flash_kernel<<<dim3(CTQ/64, CB*CH, 2), 128, FLASH_SMEM>>>(dNk);

    // Final GEMM needs Woh.
    cudaStreamWaitEvent(0, eWo, 0);
    gemm_kernel<128,128,false,false,2><<<dim3(8, 64, 1), 128, GEMM_SMEM_128_128>>>(
        dObuf, dObuf, dWoh, dWoh, bo, bo, out, out, 2048, 1.0f, 1.0f, nullptr);
}